// round 11
// baseline (speedup 1.0000x reference)
#include <cuda_runtime.h>
#include <cstdint>
#include <math.h>

#define E    4096
#define H    32
#define D    128
#define PAST 8191
#define KTOT 8192
#define NCHUNK 256
#define CHUNK  32

#define CPS   8       // cp.async pipeline depth
#define GROWS 32      // rows per GEMV block
#define GSEGY 128     // 4096 / GROWS

// ---- device scratch (no allocations allowed) ----
__device__ float g_q[E];                        // query (biased)
__device__ float g_kv[2 * D];                   // [key_new | value_new]
__device__ float g_m[NCHUNK * H];
__device__ float g_l[NCHUNK * H];
__device__ float g_po[(size_t)NCHUNK * H * D];  // 4 MB
__device__ float g_attn[E];

// ---------------------------------------------------------------------------
__global__ void init_kernel(const float* __restrict__ qb,
                            const float* __restrict__ kvb) {
    int t = blockIdx.x * blockDim.x + threadIdx.x;
    if (t < E) g_q[t] = qb[t];
    if (t < 2 * D) g_kv[t] = kvb[t];
}

__global__ void nop_kernel() {}

// ---------------------------------------------------------------------------
// cp.async helpers
// ---------------------------------------------------------------------------
__device__ __forceinline__ void cp_async16(unsigned int saddr, const void* gaddr) {
    asm volatile("cp.async.cg.shared.global [%0], [%1], 16;\n"
                 :: "r"(saddr), "l"(gaddr) : "memory");
}
__device__ __forceinline__ void cp_commit() {
    asm volatile("cp.async.commit_group;\n" ::: "memory");
}
template <int N>
__device__ __forceinline__ void cp_wait() {
    asm volatile("cp.async.wait_group %0;\n" :: "n"(N) : "memory");
}

// ---------------------------------------------------------------------------
// Fused q+kv GEMV via cp.async. grid (5, 128), 256 threads, 32 rows/block.
//   x < 4 : q path, cols [x*1024, x*1024+1024)
//   x == 4: kv path, 256 cols (threads 0..63 active)
// Each thread copies ITS OWN 16B per row into its smem slot and consumes it
// -> per-thread wait_group ordering, no __syncthreads in the loop.
// ---------------------------------------------------------------------------
__global__ void __launch_bounds__(256)
gemv_fused_cp(const float* __restrict__ x,
              const float* __restrict__ Wq,
              const float* __restrict__ Wkv) {
    __shared__ float buf[CPS * 1024];
    __shared__ float xs[GROWS];

    const int t  = threadIdx.x;
    const int i0 = blockIdx.y * GROWS;

    if (t < GROWS) xs[t] = x[i0 + t];

    const bool qpath = (blockIdx.x < 4);
    const bool active = qpath | (t < 64);
    const int  ncols = qpath ? E : 256;
    const int  j     = qpath ? (blockIdx.x * 1024 + t * 4) : ((t & 63) * 4);
    const float* wb  = (qpath ? Wq : Wkv) + (size_t)i0 * ncols + j;

    unsigned int slot = (unsigned int)__cvta_generic_to_shared(&buf[t * 4]);

    // prologue: issue first CPS rows
#pragma unroll
    for (int i = 0; i < CPS; i++) {
        if (active) cp_async16(slot + (unsigned int)i * 4096u,
                               wb + (size_t)i * ncols);
        cp_commit();
    }
    __syncthreads();   // xs visible to all

    float a0 = 0.f, a1 = 0.f, a2 = 0.f, a3 = 0.f;

    // main loop
#pragma unroll 4
    for (int i = 0; i < GROWS - CPS; i++) {
        cp_wait<CPS - 1>();
        if (active) {
            float4 w = *(const float4*)&buf[(i & (CPS - 1)) * 1024 + t * 4];
            float xv = xs[i];
            a0 += xv * w.x; a1 += xv * w.y; a2 += xv * w.z; a3 += xv * w.w;
        }
        if (active) cp_async16(slot + (unsigned int)((i + CPS) & (CPS - 1)) * 4096u,
                               wb + (size_t)(i + CPS) * ncols);
        cp_commit();
    }
    // drain
    cp_wait<0>();
    if (active) {
#pragma unroll
        for (int i = GROWS - CPS; i < GROWS; i++) {
            float4 w = *(const float4*)&buf[(i & (CPS - 1)) * 1024 + t * 4];
            float xv = xs[i];
            a0 += xv * w.x; a1 += xv * w.y; a2 += xv * w.z; a3 += xv * w.w;
        }
        float* dst = qpath ? &g_q[j] : &g_kv[j];
        atomicAdd(&dst[0], a0);
        atomicAdd(&dst[1], a1);
        atomicAdd(&dst[2], a2);
        atomicAdd(&dst[3], a3);
    }
}

// ---------------------------------------------------------------------------
// Output-projection GEMV via cp.async. grid (4, 128), 256 threads.
// out pre-seeded with proj bias by combine_kernel.
// ---------------------------------------------------------------------------
__global__ void __launch_bounds__(256)
gemv_cp_atomic(const float* __restrict__ x,
               const float* __restrict__ W,
               float* __restrict__ out) {
    __shared__ float buf[CPS * 1024];
    __shared__ float xs[GROWS];

    const int t  = threadIdx.x;
    const int i0 = blockIdx.y * GROWS;

    if (t < GROWS) xs[t] = x[i0 + t];

    const int j = blockIdx.x * 1024 + t * 4;
    const float* wb = W + (size_t)i0 * E + j;
    unsigned int slot = (unsigned int)__cvta_generic_to_shared(&buf[t * 4]);

#pragma unroll
    for (int i = 0; i < CPS; i++) {
        cp_async16(slot + (unsigned int)i * 4096u, wb + (size_t)i * E);
        cp_commit();
    }
    __syncthreads();

    float a0 = 0.f, a1 = 0.f, a2 = 0.f, a3 = 0.f;
#pragma unroll 4
    for (int i = 0; i < GROWS - CPS; i++) {
        cp_wait<CPS - 1>();
        float4 w = *(const float4*)&buf[(i & (CPS - 1)) * 1024 + t * 4];
        float xv = xs[i];
        a0 += xv * w.x; a1 += xv * w.y; a2 += xv * w.z; a3 += xv * w.w;
        cp_async16(slot + (unsigned int)((i + CPS) & (CPS - 1)) * 4096u,
                   wb + (size_t)(i + CPS) * E);
        cp_commit();
    }
    cp_wait<0>();
#pragma unroll
    for (int i = GROWS - CPS; i < GROWS; i++) {
        float4 w = *(const float4*)&buf[(i & (CPS - 1)) * 1024 + t * 4];
        float xv = xs[i];
        a0 += xv * w.x; a1 += xv * w.y; a2 += xv * w.z; a3 += xv * w.w;
    }
    atomicAdd(&out[j + 0], a0);
    atomicAdd(&out[j + 1], a1);
    atomicAdd(&out[j + 2], a2);
    atomicAdd(&out[j + 3], a3);
}

// ---------------------------------------------------------------------------
// Split-K attention partial (R4 form, measured 21.2us): 256 blocks x 128 thr,
// 32 keys per block. K/V streamed from GMEM; q + scores in smem.
// ---------------------------------------------------------------------------
__global__ void __launch_bounds__(128)
attn_partial(const float* __restrict__ pk,   // (D, PAST) d-major
             const float* __restrict__ pv,   // (PAST, D) k-major
             const float* __restrict__ mask) // (KTOT)
{
    __shared__ float qs[E];          // scaled q (h*D + d)  16 KB
    __shared__ float ss[H * CHUNK];  // scores -> weights    4 KB

    const int t = threadIdx.x;
    const int kbase = blockIdx.x * CHUNK;
    const float scale = 0.088388347648318447f; // 1/sqrt(128)

#pragma unroll
    for (int i = t * 4; i < E; i += 128 * 4) {
        float4 v = *(const float4*)&g_q[i];
        v.x *= scale; v.y *= scale; v.z *= scale; v.w *= scale;
        *(float4*)&qs[i] = v;
    }
    __syncthreads();

    // ---- score phase: lane = key, warp w owns heads w*8..w*8+7 ----
    {
        const int lane = t & 31;
        const int w = t >> 5;
        const int kg = kbase + lane;

        const float* kp; int kstr;
        if (kg < PAST) { kp = pk + kg; kstr = PAST; }
        else           { kp = g_kv;   kstr = 1;    }

        float acc[8];
#pragma unroll
        for (int h = 0; h < 8; h++) acc[h] = 0.f;

#pragma unroll 8
        for (int d4 = 0; d4 < D / 4; d4++) {
            const int d = d4 * 4;
            float k0 = __ldg(&kp[(size_t)(d + 0) * kstr]);
            float k1 = __ldg(&kp[(size_t)(d + 1) * kstr]);
            float k2 = __ldg(&kp[(size_t)(d + 2) * kstr]);
            float k3 = __ldg(&kp[(size_t)(d + 3) * kstr]);
#pragma unroll
            for (int h = 0; h < 8; h++) {
                float4 qv = *(const float4*)&qs[(w * 8 + h) * D + d];
                acc[h] += qv.x * k0 + qv.y * k1 + qv.z * k2 + qv.w * k3;
            }
        }
        float mk = __ldg(&mask[kg]);
#pragma unroll
        for (int h = 0; h < 8; h++) ss[(w * 8 + h) * CHUNK + lane] = acc[h] + mk;
    }
    __syncthreads();

    // ---- softmax: 4 threads per head (8 keys each), shuffle reduce ----
    {
        const int h = t >> 2;
        const int j = (t & 3) * 8;
        float4 s0 = *(const float4*)&ss[h * CHUNK + j];
        float4 s1 = *(const float4*)&ss[h * CHUNK + j + 4];
        float m = fmaxf(fmaxf(fmaxf(s0.x, s0.y), fmaxf(s0.z, s0.w)),
                        fmaxf(fmaxf(s1.x, s1.y), fmaxf(s1.z, s1.w)));
        m = fmaxf(m, __shfl_xor_sync(0xffffffff, m, 1));
        m = fmaxf(m, __shfl_xor_sync(0xffffffff, m, 2));
        s0.x = __expf(s0.x - m); s0.y = __expf(s0.y - m);
        s0.z = __expf(s0.z - m); s0.w = __expf(s0.w - m);
        s1.x = __expf(s1.x - m); s1.y = __expf(s1.y - m);
        s1.z = __expf(s1.z - m); s1.w = __expf(s1.w - m);
        float l = s0.x + s0.y + s0.z + s0.w + s1.x + s1.y + s1.z + s1.w;
        l += __shfl_xor_sync(0xffffffff, l, 1);
        l += __shfl_xor_sync(0xffffffff, l, 2);
        *(float4*)&ss[h * CHUNK + j]     = s0;
        *(float4*)&ss[h * CHUNK + j + 4] = s1;
        if ((t & 3) == 0) {
            g_m[blockIdx.x * H + h] = m;
            g_l[blockIdx.x * H + h] = l;
        }
    }
    __syncthreads();

    // ---- AV phase: thread = d (0..127), 32 head accumulators ----
    {
        float o[H];
#pragma unroll
        for (int h = 0; h < H; h++) o[h] = 0.f;

#pragma unroll 2
        for (int k4 = 0; k4 < CHUNK / 4; k4++) {
            const int k = k4 * 4;
            const int kg0 = kbase + k;
            const float* v0p = (kg0 + 0 < PAST) ? pv + (size_t)(kg0 + 0) * D : g_kv + D;
            const float* v1p = (kg0 + 1 < PAST) ? pv + (size_t)(kg0 + 1) * D : g_kv + D;
            const float* v2p = (kg0 + 2 < PAST) ? pv + (size_t)(kg0 + 2) * D : g_kv + D;
            const float* v3p = (kg0 + 3 < PAST) ? pv + (size_t)(kg0 + 3) * D : g_kv + D;
            float v0 = __ldg(&v0p[t]);
            float v1 = __ldg(&v1p[t]);
            float v2 = __ldg(&v2p[t]);
            float v3 = __ldg(&v3p[t]);
#pragma unroll
            for (int h = 0; h < H; h++) {
                float4 wv = *(const float4*)&ss[h * CHUNK + k];
                o[h] += wv.x * v0 + wv.y * v1 + wv.z * v2 + wv.w * v3;
            }
        }
#pragma unroll
        for (int h = 0; h < H; h++)
            g_po[((size_t)blockIdx.x * H + h) * D + t] = o[h];
    }
}

// ---------------------------------------------------------------------------
// Combine: grid 65 blocks, 256 threads.
// Blocks 0..63: (h = b>>1, half = b&1). Block 64: bias seed + kv tail.
// ---------------------------------------------------------------------------
__global__ void combine_kernel(const float* __restrict__ proj_b,
                               float* __restrict__ out) {
    if (blockIdx.x == 64) {
        for (int j = threadIdx.x; j < E; j += blockDim.x) out[j] = proj_b[j];
        if (threadIdx.x < D) {
            out[E + threadIdx.x]     = g_kv[threadIdx.x];       // key_perm
            out[E + D + threadIdx.x] = g_kv[D + threadIdx.x];   // value_new
        }
        return;
    }
    const int h    = blockIdx.x >> 1;
    const int half = blockIdx.x & 1;
    const int t    = threadIdx.x;

    __shared__ float red[256];
    __shared__ float sc[NCHUNK];

    float mv = g_m[t * H + h];
    red[t] = mv;
    __syncthreads();
#pragma unroll
    for (int s = 128; s > 0; s >>= 1) {
        if (t < s) red[t] = fmaxf(red[t], red[t + s]);
        __syncthreads();
    }
    const float m = red[0];
    __syncthreads();

    float e = __expf(mv - m);
    sc[t] = e;
    red[t] = e * g_l[t * H + h];
    __syncthreads();
#pragma unroll
    for (int s = 128; s > 0; s >>= 1) {
        if (t < s) red[t] += red[t + s];
        __syncthreads();
    }
    const float L = red[0];
    __syncthreads();

    const int d = half * 64 + (t & 63);
    const int q = t >> 6;
    float o = 0.f;
#pragma unroll 8
    for (int c = q * 64; c < q * 64 + 64; c++)
        o += __ldg(&g_po[((size_t)c * H + h) * D + d]) * sc[c];
    red[t] = o;
    __syncthreads();
    if (t < 64) {
        float oo = red[t] + red[t + 64] + red[t + 128] + red[t + 192];
        g_attn[h * D + half * 64 + t] = oo / L;
    }
}

// ---------------------------------------------------------------------------
extern "C" void kernel_launch(void* const* d_in, const int* in_sizes, int n_in,
                              void* d_out, int out_size) {
    const float* hs   = (const float*)d_in[0];
    const float* pk   = (const float*)d_in[1];
    const float* pv   = (const float*)d_in[2];
    const float* mask = (const float*)d_in[3];
    const float* qw   = (const float*)d_in[4];
    const float* qb   = (const float*)d_in[5];
    const float* kvw  = (const float*)d_in[6];
    const float* kvb  = (const float*)d_in[7];
    const float* pw   = (const float*)d_in[8];
    const float* pb   = (const float*)d_in[9];
    float* out = (float*)d_out;

    float *gattn = nullptr;
    cudaGetSymbolAddress((void**)&gattn, g_attn);

    // 1) seed biases (resets atomic accumulators every replay)
    init_kernel<<<16, 256>>>(qb, kvb);

    // 2,3) nops so profiled launch (#4) is the big GEMV
    nop_kernel<<<1, 32>>>();
    nop_kernel<<<1, 32>>>();

    // 4) q + kv GEMV via cp.async  <-- PROFILED
    gemv_fused_cp<<<dim3(5, GSEGY), 256>>>(hs, qw, kvw);

    // 5) split-K attention partials (256 chunks of 32 keys)
    attn_partial<<<NCHUNK, 128>>>(pk, pv, mask);

    // 6) merge partials; seed output with proj bias; write kv tail
    combine_kernel<<<65, 256>>>(pb, out);

    // 7) out[0:4096] += attn @ proj_w
    gemv_cp_atomic<<<dim3(4, GSEGY), 256>>>(gattn, pw, out);
}

// round 13
// speedup vs baseline: 1.2674x; 1.2674x over previous
#include <cuda_runtime.h>
#include <cstdint>
#include <math.h>

#define E    4096
#define H    32
#define D    128
#define PAST 8191
#define KTOT 8192
#define NCHUNK 256
#define CHUNK  32

#define CPS   8       // cp.async pipeline depth (GEMV)
#define GROWS 64      // rows per GEMV block (R10 proven)
#define GSEGY 64      // 4096 / GROWS

// ---- device scratch (no allocations allowed) ----
__device__ float g_q[E];                        // query (biased)
__device__ float g_kv[2 * D];                   // [key_new | value_new]
__device__ float g_m[NCHUNK * H];
__device__ float g_l[NCHUNK * H];
__device__ float g_po[(size_t)NCHUNK * H * D];  // 4 MB
__device__ float g_attn[E];

// ---------------------------------------------------------------------------
__global__ void init_kernel(const float* __restrict__ qb,
                            const float* __restrict__ kvb) {
    int t = blockIdx.x * blockDim.x + threadIdx.x;
    if (t < E) g_q[t] = qb[t];
    if (t < 2 * D) g_kv[t] = kvb[t];
}

__global__ void nop_kernel() {}

// ---------------------------------------------------------------------------
// cp.async helpers
// ---------------------------------------------------------------------------
__device__ __forceinline__ void cp_async16(unsigned int saddr, const void* gaddr) {
    asm volatile("cp.async.cg.shared.global [%0], [%1], 16;\n"
                 :: "r"(saddr), "l"(gaddr) : "memory");
}
__device__ __forceinline__ void cp_async4(unsigned int saddr, const void* gaddr) {
    asm volatile("cp.async.ca.shared.global [%0], [%1], 4;\n"
                 :: "r"(saddr), "l"(gaddr) : "memory");
}
__device__ __forceinline__ void cp_commit() {
    asm volatile("cp.async.commit_group;\n" ::: "memory");
}
template <int N>
__device__ __forceinline__ void cp_wait() {
    asm volatile("cp.async.wait_group %0;\n" :: "n"(N) : "memory");
}

// ---------------------------------------------------------------------------
// Fused q+kv GEMV via cp.async (R10 proven: 17.1us, 4.19 TB/s).
// grid (5, 64), 256 threads, 64 rows/block.
// ---------------------------------------------------------------------------
__global__ void __launch_bounds__(256)
gemv_fused_cp(const float* __restrict__ x,
              const float* __restrict__ Wq,
              const float* __restrict__ Wkv) {
    __shared__ float buf[CPS * 1024];
    __shared__ float xs[GROWS];

    const int t  = threadIdx.x;
    const int i0 = blockIdx.y * GROWS;

    for (int i = t; i < GROWS; i += 256) xs[i] = x[i0 + i];

    const bool qpath = (blockIdx.x < 4);
    const bool active = qpath | (t < 64);
    const int  ncols = qpath ? E : 256;
    const int  j     = qpath ? (blockIdx.x * 1024 + t * 4) : ((t & 63) * 4);
    const float* wb  = (qpath ? Wq : Wkv) + (size_t)i0 * ncols + j;

    unsigned int slot = (unsigned int)__cvta_generic_to_shared(&buf[t * 4]);

#pragma unroll
    for (int i = 0; i < CPS; i++) {
        if (active) cp_async16(slot + (unsigned int)i * 4096u,
                               wb + (size_t)i * ncols);
        cp_commit();
    }
    __syncthreads();

    float a0 = 0.f, a1 = 0.f, a2 = 0.f, a3 = 0.f;

#pragma unroll 4
    for (int i = 0; i < GROWS - CPS; i++) {
        cp_wait<CPS - 1>();
        if (active) {
            float4 w = *(const float4*)&buf[(i & (CPS - 1)) * 1024 + t * 4];
            float xv = xs[i];
            a0 += xv * w.x; a1 += xv * w.y; a2 += xv * w.z; a3 += xv * w.w;
        }
        if (active) cp_async16(slot + (unsigned int)((i + CPS) & (CPS - 1)) * 4096u,
                               wb + (size_t)(i + CPS) * ncols);
        cp_commit();
    }
    cp_wait<0>();
    if (active) {
#pragma unroll
        for (int i = GROWS - CPS; i < GROWS; i++) {
            float4 w = *(const float4*)&buf[(i & (CPS - 1)) * 1024 + t * 4];
            float xv = xs[i];
            a0 += xv * w.x; a1 += xv * w.y; a2 += xv * w.z; a3 += xv * w.w;
        }
        float* dst = qpath ? &g_q[j] : &g_kv[j];
        atomicAdd(&dst[0], a0);
        atomicAdd(&dst[1], a1);
        atomicAdd(&dst[2], a2);
        atomicAdd(&dst[3], a3);
    }
}

// ---------------------------------------------------------------------------
// Output-projection GEMV via cp.async (R10 form). grid (4, 64), 256 threads.
// ---------------------------------------------------------------------------
__global__ void __launch_bounds__(256)
gemv_cp_atomic(const float* __restrict__ x,
               const float* __restrict__ W,
               float* __restrict__ out) {
    __shared__ float buf[CPS * 1024];
    __shared__ float xs[GROWS];

    const int t  = threadIdx.x;
    const int i0 = blockIdx.y * GROWS;

    for (int i = t; i < GROWS; i += 256) xs[i] = x[i0 + i];

    const int j = blockIdx.x * 1024 + t * 4;
    const float* wb = W + (size_t)i0 * E + j;
    unsigned int slot = (unsigned int)__cvta_generic_to_shared(&buf[t * 4]);

#pragma unroll
    for (int i = 0; i < CPS; i++) {
        cp_async16(slot + (unsigned int)i * 4096u, wb + (size_t)i * E);
        cp_commit();
    }
    __syncthreads();

    float a0 = 0.f, a1 = 0.f, a2 = 0.f, a3 = 0.f;
#pragma unroll 4
    for (int i = 0; i < GROWS - CPS; i++) {
        cp_wait<CPS - 1>();
        float4 w = *(const float4*)&buf[(i & (CPS - 1)) * 1024 + t * 4];
        float xv = xs[i];
        a0 += xv * w.x; a1 += xv * w.y; a2 += xv * w.z; a3 += xv * w.w;
        cp_async16(slot + (unsigned int)((i + CPS) & (CPS - 1)) * 4096u,
                   wb + (size_t)(i + CPS) * E);
        cp_commit();
    }
    cp_wait<0>();
#pragma unroll
    for (int i = GROWS - CPS; i < GROWS; i++) {
        float4 w = *(const float4*)&buf[(i & (CPS - 1)) * 1024 + t * 4];
        float xv = xs[i];
        a0 += xv * w.x; a1 += xv * w.y; a2 += xv * w.z; a3 += xv * w.w;
    }
    atomicAdd(&out[j + 0], a0);
    atomicAdd(&out[j + 1], a1);
    atomicAdd(&out[j + 2], a2);
    atomicAdd(&out[j + 3], a3);
}

// ---------------------------------------------------------------------------
// Split-K attention partial v6b: 256 blocks x 128 threads, 32 keys per block.
// K tile via cp.async.ca 4B (8191-stride rows are not 16B-aligned);
// V tile via cp.async.cg 16B. Both overlapped with q staging.
// Dynamic smem: qs[E] | kt[D*CHUNK] | vt[CHUNK*D] | ss[H*CHUNK]  = 52 KB
// ---------------------------------------------------------------------------
__global__ void __launch_bounds__(128)
attn_partial(const float* __restrict__ pk,   // (D, PAST) d-major
             const float* __restrict__ pv,   // (PAST, D) k-major
             const float* __restrict__ mask) // (KTOT)
{
    extern __shared__ float smem[];
    float* qs = smem;                              // E
    float* kt = smem + E;                          // D*CHUNK   [d*32 + k]
    float* vt = smem + E + D * CHUNK;              // CHUNK*D   [k*128 + d]
    float* ss = smem + E + 2 * D * CHUNK;          // H*CHUNK

    const int t = threadIdx.x;
    const int kbase = blockIdx.x * CHUNK;
    const float scale = 0.088388347648318447f; // 1/sqrt(128)
    const bool last = (kbase + CHUNK > PAST);  // only block 255

    if (!last) {
        unsigned int kdst = (unsigned int)__cvta_generic_to_shared(kt);
        unsigned int vdst = (unsigned int)__cvta_generic_to_shared(vt);
        // K tile: 4096 floats via 4B ca-copies; elem e -> d = e>>5, k = e&31
        // (warp covers one 32-key row -> 128B contiguous gmem per warp)
#pragma unroll
        for (int e = t; e < D * CHUNK; e += 128) {
            const int d = e >> 5, k = e & 31;
            cp_async4(kdst + (unsigned int)e * 4u,
                      pk + (size_t)d * PAST + kbase + k);
        }
        cp_commit();   // group 1-of-2 pending after V commit
        // V tile: 1024 16B units; unit u -> k = u>>5, d16 = u&31
#pragma unroll
        for (int u = t; u < (CHUNK * D) / 4; u += 128) {
            const int k = u >> 5, d16 = u & 31;
            cp_async16(vdst + (unsigned int)u * 16u,
                       pv + (size_t)(kbase + k) * D + d16 * 4);
        }
        cp_commit();
    }

    // q staging (overlaps with the cp.async tile fetches)
#pragma unroll
    for (int i = t * 4; i < E; i += 128 * 4) {
        float4 v = *(const float4*)&g_q[i];
        v.x *= scale; v.y *= scale; v.z *= scale; v.w *= scale;
        *(float4*)&qs[i] = v;
    }

    if (!last) {
        cp_wait<1>();          // K tile complete (this thread's units)
    } else {
        // scalar fallback for the boundary block
        for (int idx = t; idx < D * CHUNK; idx += 128) {
            const int d = idx >> 5, k = idx & 31;
            const int kg = kbase + k;
            kt[idx] = (kg < PAST) ? pk[(size_t)d * PAST + kg] : g_kv[d];
        }
        for (int idx = t; idx < CHUNK * D; idx += 128) {
            const int k = idx >> 7, d = idx & 127;
            const int kg = kbase + k;
            vt[idx] = (kg < PAST) ? pv[(size_t)kg * D + d] : g_kv[D + d];
        }
    }
    __syncthreads();   // K tile + q globally visible

    // ---- score phase: lane = key, warp w owns heads w*8..w*8+7 ----
    {
        const int lane = t & 31;
        const int w = t >> 5;

        float acc[8];
#pragma unroll
        for (int h = 0; h < 8; h++) acc[h] = 0.f;

#pragma unroll 8
        for (int d4 = 0; d4 < D / 4; d4++) {
            const int d = d4 * 4;
            float k0 = kt[(d + 0) * CHUNK + lane];
            float k1 = kt[(d + 1) * CHUNK + lane];
            float k2 = kt[(d + 2) * CHUNK + lane];
            float k3 = kt[(d + 3) * CHUNK + lane];
#pragma unroll
            for (int h = 0; h < 8; h++) {
                float4 qv = *(const float4*)&qs[(w * 8 + h) * D + d];
                acc[h] += qv.x * k0 + qv.y * k1 + qv.z * k2 + qv.w * k3;
            }
        }
        float mk = __ldg(&mask[kbase + lane]);
#pragma unroll
        for (int h = 0; h < 8; h++) ss[(w * 8 + h) * CHUNK + lane] = acc[h] + mk;
    }
    __syncthreads();

    // ---- softmax: 4 threads per head (8 keys each), shuffle reduce ----
    {
        const int h = t >> 2;
        const int j = (t & 3) * 8;
        float4 s0 = *(const float4*)&ss[h * CHUNK + j];
        float4 s1 = *(const float4*)&ss[h * CHUNK + j + 4];
        float m = fmaxf(fmaxf(fmaxf(s0.x, s0.y), fmaxf(s0.z, s0.w)),
                        fmaxf(fmaxf(s1.x, s1.y), fmaxf(s1.z, s1.w)));
        m = fmaxf(m, __shfl_xor_sync(0xffffffff, m, 1));
        m = fmaxf(m, __shfl_xor_sync(0xffffffff, m, 2));
        s0.x = __expf(s0.x - m); s0.y = __expf(s0.y - m);
        s0.z = __expf(s0.z - m); s0.w = __expf(s0.w - m);
        s1.x = __expf(s1.x - m); s1.y = __expf(s1.y - m);
        s1.z = __expf(s1.z - m); s1.w = __expf(s1.w - m);
        float l = s0.x + s0.y + s0.z + s0.w + s1.x + s1.y + s1.z + s1.w;
        l += __shfl_xor_sync(0xffffffff, l, 1);
        l += __shfl_xor_sync(0xffffffff, l, 2);
        *(float4*)&ss[h * CHUNK + j]     = s0;
        *(float4*)&ss[h * CHUNK + j + 4] = s1;
        if ((t & 3) == 0) {
            g_m[blockIdx.x * H + h] = m;
            g_l[blockIdx.x * H + h] = l;
        }
    }
    if (!last) cp_wait<0>();   // V tile complete (this thread's units)
    __syncthreads();           // ss + V globally visible

    // ---- AV phase: thread = d (0..127), 32 head accumulators ----
    {
        float o[H];
#pragma unroll
        for (int h = 0; h < H; h++) o[h] = 0.f;

#pragma unroll 2
        for (int k4 = 0; k4 < CHUNK / 4; k4++) {
            const int k = k4 * 4;
            float v0 = vt[(k + 0) * D + t];
            float v1 = vt[(k + 1) * D + t];
            float v2 = vt[(k + 2) * D + t];
            float v3 = vt[(k + 3) * D + t];
#pragma unroll
            for (int h = 0; h < H; h++) {
                float4 wv = *(const float4*)&ss[h * CHUNK + k];
                o[h] += wv.x * v0 + wv.y * v1 + wv.z * v2 + wv.w * v3;
            }
        }
#pragma unroll
        for (int h = 0; h < H; h++)
            g_po[((size_t)blockIdx.x * H + h) * D + t] = o[h];
    }
}

// ---------------------------------------------------------------------------
// Combine: grid 65 blocks, 256 threads.
// Blocks 0..63: (h = b>>1, half = b&1). Block 64: bias seed + kv tail.
// ---------------------------------------------------------------------------
__global__ void combine_kernel(const float* __restrict__ proj_b,
                               float* __restrict__ out) {
    if (blockIdx.x == 64) {
        for (int j = threadIdx.x; j < E; j += blockDim.x) out[j] = proj_b[j];
        if (threadIdx.x < D) {
            out[E + threadIdx.x]     = g_kv[threadIdx.x];       // key_perm
            out[E + D + threadIdx.x] = g_kv[D + threadIdx.x];   // value_new
        }
        return;
    }
    const int h    = blockIdx.x >> 1;
    const int half = blockIdx.x & 1;
    const int t    = threadIdx.x;

    __shared__ float red[256];
    __shared__ float sc[NCHUNK];

    float mv = g_m[t * H + h];
    red[t] = mv;
    __syncthreads();
#pragma unroll
    for (int s = 128; s > 0; s >>= 1) {
        if (t < s) red[t] = fmaxf(red[t], red[t + s]);
        __syncthreads();
    }
    const float m = red[0];
    __syncthreads();

    float e = __expf(mv - m);
    sc[t] = e;
    red[t] = e * g_l[t * H + h];
    __syncthreads();
#pragma unroll
    for (int s = 128; s > 0; s >>= 1) {
        if (t < s) red[t] += red[t + s];
        __syncthreads();
    }
    const float L = red[0];
    __syncthreads();

    const int d = half * 64 + (t & 63);
    const int q = t >> 6;
    float o = 0.f;
#pragma unroll 8
    for (int c = q * 64; c < q * 64 + 64; c++)
        o += __ldg(&g_po[((size_t)c * H + h) * D + d]) * sc[c];
    red[t] = o;
    __syncthreads();
    if (t < 64) {
        float oo = red[t] + red[t + 64] + red[t + 128] + red[t + 192];
        g_attn[h * D + half * 64 + t] = oo / L;
    }
}

// ---------------------------------------------------------------------------
extern "C" void kernel_launch(void* const* d_in, const int* in_sizes, int n_in,
                              void* d_out, int out_size) {
    const float* hs   = (const float*)d_in[0];
    const float* pk   = (const float*)d_in[1];
    const float* pv   = (const float*)d_in[2];
    const float* mask = (const float*)d_in[3];
    const float* qw   = (const float*)d_in[4];
    const float* qb   = (const float*)d_in[5];
    const float* kvw  = (const float*)d_in[6];
    const float* kvb  = (const float*)d_in[7];
    const float* pw   = (const float*)d_in[8];
    const float* pb   = (const float*)d_in[9];
    float* out = (float*)d_out;

    float *gattn = nullptr;
    cudaGetSymbolAddress((void**)&gattn, g_attn);

    const int attn_smem = (E + 2 * D * CHUNK + H * CHUNK) * (int)sizeof(float); // 52 KB
    static int smem_set = 0;
    if (!smem_set) {
        cudaFuncSetAttribute(attn_partial,
                             cudaFuncAttributeMaxDynamicSharedMemorySize,
                             attn_smem);
        smem_set = 1;
    }

    // 1) seed biases (resets atomic accumulators every replay)
    init_kernel<<<16, 256>>>(qb, kvb);

    // 2) q + kv GEMV via cp.async (R10 proven)
    gemv_fused_cp<<<dim3(5, GSEGY), 256>>>(hs, qw, kvw);

    // 3) nop so profiled launch (#4) is attn
    nop_kernel<<<1, 32>>>();

    // 4) split-K attention partials (cp.async tiles)  <-- PROFILED
    attn_partial<<<NCHUNK, 128, attn_smem>>>(pk, pv, mask);

    // 5) merge partials; seed output with proj bias; write kv tail
    combine_kernel<<<65, 256>>>(pb, out);

    // 6) out[0:4096] += attn @ proj_w
    gemv_cp_atomic<<<dim3(4, GSEGY), 256>>>(gattn, pw, out);
}